// round 14
// baseline (speedup 1.0000x reference)
#include <cuda_runtime.h>
#include <cuda_bf16.h>
#include <math.h>
#include <stdint.h>

#define N0c 100000
#define N1c 200000
#define NNZc 400000
#define Dc 256

// ---------------- scratch (device globals; no allocation allowed) ----------
__device__ float g_msgA[(size_t)N0c * 128];      // X @ W[:,0:128)   (51.2 MB)
__device__ float g_msgB[(size_t)N0c * 128];      // X @ W[:,128:256) (51.2 MB)
__device__ __nv_bfloat16 g_WtH[Dc * Dc];         // W^T hi, [n][k]
__device__ __nv_bfloat16 g_WtL[Dc * Dc];         // W^T lo, [n][k]
__device__ int   g_count[N1c];
__device__ int   g_start[N1c];
__device__ int   g_cursor[N1c];
__device__ int2  g_epack[NNZc];                  // (col, val bits)
__device__ int   g_bsums[128];

// ================= helpers ===================================================
__device__ __forceinline__ uint32_t smem_u32(const void* p) {
    uint32_t a;
    asm("{ .reg .u64 t; cvta.to.shared.u64 t, %1; cvt.u32.u64 %0, t; }"
        : "=r"(a) : "l"(p));
    return a;
}
__device__ __forceinline__ void cp_async16(uint32_t dst, const void* src, int sz) {
    asm volatile("cp.async.cg.shared.global [%0], [%1], 16, %2;"
                 :: "r"(dst), "l"(__cvta_generic_to_global(src)), "r"(sz) : "memory");
}
#define CP_COMMIT() asm volatile("cp.async.commit_group;" ::: "memory")
#define CP_WAIT0()  asm volatile("cp.async.wait_group 0;" ::: "memory")
#define LDSM4(r, a) \
    asm volatile("ldmatrix.sync.aligned.m8n8.x4.shared.b16 {%0,%1,%2,%3}, [%4];" \
        : "=r"((r)[0]), "=r"((r)[1]), "=r"((r)[2]), "=r"((r)[3]) : "r"(a))

__device__ __forceinline__ void mma16816(float* c, const uint32_t* a,
                                         uint32_t b0, uint32_t b1) {
    asm volatile(
        "mma.sync.aligned.m16n8k16.row.col.f32.bf16.bf16.f32 "
        "{%0,%1,%2,%3}, {%4,%5,%6,%7}, {%8,%9}, {%0,%1,%2,%3};\n"
        : "+f"(c[0]), "+f"(c[1]), "+f"(c[2]), "+f"(c[3])
        : "r"(a[0]), "r"(a[1]), "r"(a[2]), "r"(a[3]), "r"(b0), "r"(b1));
}

// ---------------- CSR build --------------------------------------------------
__global__ void k_zero_count() {
    int i = blockIdx.x * blockDim.x + threadIdx.x;
    if (i < N1c) g_count[i] = 0;
}

__global__ void k_hist(const int* __restrict__ rows) {
    int i = blockIdx.x * blockDim.x + threadIdx.x;
    if (i < NNZc) atomicAdd(&g_count[rows[i]], 1);
}

__global__ void k_scan_a() {
    __shared__ int s[256];
    int tid  = threadIdx.x;
    int base = blockIdx.x * 2048;
    int vals[8];
    int sum = 0;
#pragma unroll
    for (int i = 0; i < 8; i++) {
        int idx = base + tid * 8 + i;
        int v = (idx < N1c) ? g_count[idx] : 0;
        vals[i] = sum;
        sum += v;
    }
    s[tid] = sum;
    __syncthreads();
    for (int off = 1; off < 256; off <<= 1) {
        int t = (tid >= off) ? s[tid - off] : 0;
        __syncthreads();
        s[tid] += t;
        __syncthreads();
    }
    int ex = s[tid] - sum;
#pragma unroll
    for (int i = 0; i < 8; i++) {
        int idx = base + tid * 8 + i;
        if (idx < N1c) g_start[idx] = ex + vals[i];
    }
    if (tid == 255) g_bsums[blockIdx.x] = s[255];
}

__global__ void k_scan_b(int nblk) {
    __shared__ int s[128];
    int tid = threadIdx.x;
    int v = (tid < nblk) ? g_bsums[tid] : 0;
    s[tid] = v;
    __syncthreads();
    for (int off = 1; off < 128; off <<= 1) {
        int t = (tid >= off) ? s[tid - off] : 0;
        __syncthreads();
        s[tid] += t;
        __syncthreads();
    }
    if (tid < nblk) g_bsums[tid] = s[tid] - v;
}

__global__ void k_scan_c() {
    int i = blockIdx.x * blockDim.x + threadIdx.x;
    if (i < N1c) {
        int v = g_start[i] + g_bsums[i >> 11];
        g_start[i]  = v;
        g_cursor[i] = v;
    }
}

__global__ void k_scatter(const int* __restrict__ rows, const int* __restrict__ cols,
                          const float* __restrict__ vals) {
    int e = blockIdx.x * blockDim.x + threadIdx.x;
    if (e < NNZc) {
        int p = atomicAdd(&g_cursor[rows[e]], 1);
        g_epack[p] = make_int2(cols[e], __float_as_int(vals[e]));
    }
}

// ---------------- prep: W transpose + bf16 hi/lo split -----------------------
__global__ void k_wprep(const float* __restrict__ W) {
    int i = blockIdx.x * 256 + threadIdx.x;      // 0..65535
    int n = i >> 8, k = i & 255;
    float v = W[k * Dc + n];
    __nv_bfloat16 h = __float2bfloat16(v);
    __nv_bfloat16 l = __float2bfloat16(v - __bfloat162float(h));
    g_WtH[i] = h;
    g_WtL[i] = l;
}

// ---------------- GEMM half: msg = X @ W[:, n0:n0+128) -----------------------
// CTA: 64(M) x 128(N), BK=32, 256 threads (8 warps 2x4, warp tile 32x32),
// 2 CTAs/SM, fused fp32->bf16 split in smem, 2-stage cp.async.
// 80B-padded rows: ldmatrix banks (20*i)%32 conflict-free.
#define RAW_STG  8192                // 64 x 32 fp32
#define B_SIDE   10240               // 128 x 40 bf16 (one of hi/lo)
#define B_STAGE  20480
#define OFF_B    16384               // 2 * RAW_STG
#define OFF_CAH  57344               // OFF_B + 2 * B_STAGE
#define OFF_CAL  62464               // OFF_CAH + 5120
#define GEMM_SMEM 67584

__device__ __forceinline__ void load_stage(uint32_t sb, int st, int m0, int n0,
                                           int tid, const float* X) {
    const int kb = st * 32;
    // raw A: 64 rows x 128B, 512 16B-chunks over 256 threads
    const uint32_t rawb = sb + (st & 1) * RAW_STG;
#pragma unroll
    for (int i = 0; i < 2; i++) {
        int idx = tid + (i << 8);
        int r = idx >> 3, c = idx & 7;
        int gm = m0 + r;
        int ok = (gm < N0c) ? 16 : 0;          // sz=0 -> zero-fill
        int rr = gm < N0c ? gm : N0c - 1;
        cp_async16(rawb + r * 128 + c * 16, X + (size_t)rr * Dc + kb + 4 * c, ok);
    }
    // B: WtH/WtL half tiles (rows n0..n0+127), 1024 16B-chunks
    const uint32_t bb = sb + OFF_B + (st & 1) * B_STAGE;
#pragma unroll
    for (int i = 0; i < 4; i++) {
        int idx = tid + (i << 8);
        int side = idx >> 9, r = (idx >> 2) & 127, c = idx & 3;
        const __nv_bfloat16* src = (side ? g_WtL : g_WtH) + (n0 + r) * Dc + kb + 8 * c;
        cp_async16(bb + side * B_SIDE + r * 80 + c * 16, src, 16);
    }
}

__global__ __launch_bounds__(256, 2)
void k_gemm(const float* __restrict__ X, float* __restrict__ msg, int n0) {
    extern __shared__ char smem[];
    const int tid = threadIdx.x;
    const int w = tid >> 5, l = tid & 31;
    const int m0 = blockIdx.x * 64;
    const uint32_t sb = smem_u32(smem);

    const int wm = (w >> 2) * 32;     // 2 (m) x 4 (n) warp grid, 32x32 tiles
    const int wn = (w & 3) * 32;
    const int ra  = (l & 7) + ((l >> 3) & 1) * 8;
    const int kca = (l >> 4) * 8;
    const int rb  = (l & 7) + (l >> 4) * 8;
    const int kcb = ((l >> 3) & 1) * 8;

    float acc[2][4][4];
#pragma unroll
    for (int a = 0; a < 2; a++)
#pragma unroll
        for (int b = 0; b < 4; b++)
#pragma unroll
            for (int c = 0; c < 4; c++) acc[a][b][c] = 0.f;

    load_stage(sb, 0, m0, n0, tid, X); CP_COMMIT();

    for (int kt = 0; kt < 8; kt++) {
        CP_WAIT0();
        __syncthreads();                     // stage kt ready; prev compute done
        if (kt < 7) { load_stage(sb, kt + 1, m0, n0, tid, X); CP_COMMIT(); }

        // convert raw fp32 stage kt -> bf16 hi/lo conv buffers
        {
            const char* rawp = smem + (kt & 1) * RAW_STG;
#pragma unroll
            for (int i = 0; i < 2; i++) {
                int idx = tid + (i << 8);
                int r = idx >> 3, c4 = (idx & 7) << 2;
                float4 v = *(const float4*)(rawp + r * 128 + (c4 << 2));
                float vv[4] = {v.x, v.y, v.z, v.w};
                uint32_t hp[2], lp[2];
#pragma unroll
                for (int j = 0; j < 2; j++) {
                    __nv_bfloat16 h0 = __float2bfloat16(vv[2 * j]);
                    __nv_bfloat16 h1 = __float2bfloat16(vv[2 * j + 1]);
                    __nv_bfloat16 l0 = __float2bfloat16(vv[2 * j] - __bfloat162float(h0));
                    __nv_bfloat16 l1 = __float2bfloat16(vv[2 * j + 1] - __bfloat162float(h1));
                    hp[j] = (uint32_t)__bfloat16_as_ushort(h0) | ((uint32_t)__bfloat16_as_ushort(h1) << 16);
                    lp[j] = (uint32_t)__bfloat16_as_ushort(l0) | ((uint32_t)__bfloat16_as_ushort(l1) << 16);
                }
                uint32_t off = r * 80 + (c4 << 1);
                *(uint2*)(smem + OFF_CAH + off) = make_uint2(hp[0], hp[1]);
                *(uint2*)(smem + OFF_CAL + off) = make_uint2(lp[0], lp[1]);
            }
        }
        __syncthreads();                     // conv buffers ready

        const uint32_t bbase = sb + OFF_B + (kt & 1) * B_STAGE;
#pragma unroll
        for (int k16 = 0; k16 < 32; k16 += 16) {
            uint32_t ah[2][4], al[2][4];
#pragma unroll
            for (int mi = 0; mi < 2; mi++) {
                uint32_t arow = sb + OFF_CAH + (wm + 16 * mi + ra) * 80 + (k16 + kca) * 2;
                LDSM4(ah[mi], arow);
                LDSM4(al[mi], arow + 5120);
            }
#pragma unroll
            for (int ng = 0; ng < 2; ng++) {
                uint32_t brow = bbase + (wn + 16 * ng + rb) * 80 + (k16 + kcb) * 2;
                uint32_t bh[4], bl[4];
                LDSM4(bh, brow);
                LDSM4(bl, brow + B_SIDE);
#pragma unroll
                for (int mi = 0; mi < 2; mi++) {
                    mma16816(acc[mi][2 * ng],     ah[mi], bh[0], bh[1]);
                    mma16816(acc[mi][2 * ng + 1], ah[mi], bh[2], bh[3]);
                }
#pragma unroll
                for (int mi = 0; mi < 2; mi++) {
                    mma16816(acc[mi][2 * ng],     al[mi], bh[0], bh[1]);
                    mma16816(acc[mi][2 * ng + 1], al[mi], bh[2], bh[3]);
                }
#pragma unroll
                for (int mi = 0; mi < 2; mi++) {
                    mma16816(acc[mi][2 * ng],     ah[mi], bl[0], bl[1]);
                    mma16816(acc[mi][2 * ng + 1], ah[mi], bl[2], bl[3]);
                }
            }
        }
    }

    // epilogue: acc -> msg half ([row][128])
#pragma unroll
    for (int mi = 0; mi < 2; mi++) {
#pragma unroll
        for (int h = 0; h < 2; h++) {
            int row = m0 + wm + 16 * mi + (l >> 2) + 8 * h;
            if (row < N0c) {
                float* dst = msg + (size_t)row * 128 + wn + 2 * (l & 3);
#pragma unroll
                for (int nj = 0; nj < 4; nj++) {
                    float2 f = make_float2(acc[mi][nj][2 * h], acc[mi][nj][2 * h + 1]);
                    *(float2*)(dst + 8 * nj) = f;
                }
            }
        }
    }
}

// ---------------- pull aggregation + elu (one 128-col half) ------------------
// 32 threads per output row (4 floats each), 8 rows per 256-thread block.
__global__ void k_agg(const float* __restrict__ msg, float* __restrict__ out,
                      int half) {
    int row = blockIdx.x * 8 + (threadIdx.x >> 5);
    int t = threadIdx.x & 31;
    if (row >= N1c) return;
    int s = g_start[row];
    int n = g_count[row];
    const float4* msg4 = (const float4*)msg;
    float4 acc = make_float4(0.f, 0.f, 0.f, 0.f);
    int j = 0;
    for (; j + 2 <= n; j += 2) {          // 2 independent gathers in flight
        int2 e0 = g_epack[s + j];
        int2 e1 = g_epack[s + j + 1];
        float v0 = __int_as_float(e0.y);
        float v1 = __int_as_float(e1.y);
        float4 m0 = msg4[(size_t)e0.x * 32 + t];
        float4 m1 = msg4[(size_t)e1.x * 32 + t];
        acc.x += v0 * m0.x + v1 * m1.x;
        acc.y += v0 * m0.y + v1 * m1.y;
        acc.z += v0 * m0.z + v1 * m1.z;
        acc.w += v0 * m0.w + v1 * m1.w;
    }
    if (j < n) {
        int2 e = g_epack[s + j];
        float v = __int_as_float(e.y);
        float4 m = msg4[(size_t)e.x * 32 + t];
        acc.x += v * m.x;
        acc.y += v * m.y;
        acc.z += v * m.z;
        acc.w += v * m.w;
    }
    acc.x = acc.x > 0.f ? acc.x : expm1f(acc.x);
    acc.y = acc.y > 0.f ? acc.y : expm1f(acc.y);
    acc.z = acc.z > 0.f ? acc.z : expm1f(acc.z);
    acc.w = acc.w > 0.f ? acc.w : expm1f(acc.w);
    ((float4*)out)[(size_t)row * 64 + half * 32 + t] = acc;
}

// ---------------- launch ------------------------------------------------------
static cudaStream_t g_s1;
static cudaEvent_t  g_evFork, g_evCSR, g_evG1, g_evA1;

extern "C" void kernel_launch(void* const* d_in, const int* in_sizes, int n_in,
                              void* d_out, int out_size) {
    const float* x0   = (const float*)d_in[0];
    const int*   rows = (const int*)d_in[2];
    const int*   cols = (const int*)d_in[3];
    const float* vals = (const float*)d_in[4];
    const float* W    = (const float*)d_in[5];
    float* out = (float*)d_out;

    static bool once = []() {
        cudaFuncSetAttribute(k_gemm, cudaFuncAttributeMaxDynamicSharedMemorySize, GEMM_SMEM);
        cudaStreamCreateWithFlags(&g_s1, cudaStreamNonBlocking);
        cudaEventCreateWithFlags(&g_evFork, cudaEventDisableTiming);
        cudaEventCreateWithFlags(&g_evCSR, cudaEventDisableTiming);
        cudaEventCreateWithFlags(&g_evG1, cudaEventDisableTiming);
        cudaEventCreateWithFlags(&g_evA1, cudaEventDisableTiming);
        return true;
    }();
    (void)once;

    float* msgA;  cudaGetSymbolAddress((void**)&msgA, g_msgA);
    float* msgB;  cudaGetSymbolAddress((void**)&msgB, g_msgB);

    cudaEventRecord(g_evFork, 0);
    cudaStreamWaitEvent(g_s1, g_evFork, 0);

    // main: wprep -> GEMM1 -> GEMM2 -> (waits) AGG2
    // s1:   CSR chain -> (waits GEMM1) AGG1 (cols 0-127, overlaps GEMM2)
    k_wprep<<<Dc, 256>>>(W);                                      // 1 (main)
    k_zero_count<<<(N1c + 255) / 256, 256, 0, g_s1>>>();          // 2 (s1)
    k_hist<<<(NNZc + 255) / 256, 256, 0, g_s1>>>(rows);           // 3 (s1)
    k_gemm<<<(N0c + 63) / 64, 256, GEMM_SMEM>>>(x0, msgA, 0);     // 4 (main) <- ncu slot
    cudaEventRecord(g_evG1, 0);
    k_scan_a<<<98, 256, 0, g_s1>>>();                             // 5 (s1)
    k_scan_b<<<1, 128, 0, g_s1>>>(98);                            // 6 (s1)
    k_scan_c<<<(N1c + 255) / 256, 256, 0, g_s1>>>();              // 7 (s1)
    k_scatter<<<(NNZc + 255) / 256, 256, 0, g_s1>>>(rows, cols, vals); // 8 (s1)
    cudaEventRecord(g_evCSR, g_s1);

    k_gemm<<<(N0c + 63) / 64, 256, GEMM_SMEM>>>(x0, msgB, 128);   // 9 (main)

    cudaStreamWaitEvent(g_s1, g_evG1, 0);
    k_agg<<<(N1c + 7) / 8, 256, 0, g_s1>>>(msgA, out, 0);         // 10 (s1, ∥ GEMM2)
    cudaEventRecord(g_evA1, g_s1);

    cudaStreamWaitEvent(0, g_evCSR, 0);
    k_agg<<<(N1c + 7) / 8, 256>>>(msgB, out, 1);                  // 11 (main)
    cudaStreamWaitEvent(0, g_evA1, 0);                            // join leaf on main
}

// round 16
// speedup vs baseline: 1.0557x; 1.0557x over previous
#include <cuda_runtime.h>
#include <cuda_bf16.h>
#include <math.h>
#include <stdint.h>

#define N0c 100000
#define N1c 200000
#define NNZc 400000
#define Dc 256

// ---------------- scratch (device globals; no allocation allowed) ----------
__device__ float g_msg[(size_t)N0c * Dc];        // x_0 @ W  (102.4 MB)
__device__ __nv_bfloat16 g_WtH[Dc * Dc];         // W^T hi, [n][k]
__device__ __nv_bfloat16 g_WtL[Dc * Dc];         // W^T lo, [n][k]
__device__ int   g_count[N1c];
__device__ int   g_start[N1c];
__device__ int   g_cursor[N1c];
__device__ int2  g_epack[NNZc];                  // (col, val bits)
__device__ int   g_bsums[128];

// ================= helpers ===================================================
__device__ __forceinline__ uint32_t smem_u32(const void* p) {
    uint32_t a;
    asm("{ .reg .u64 t; cvta.to.shared.u64 t, %1; cvt.u32.u64 %0, t; }"
        : "=r"(a) : "l"(p));
    return a;
}
__device__ __forceinline__ void cp_async16(uint32_t dst, const void* src, int sz) {
    asm volatile("cp.async.cg.shared.global [%0], [%1], 16, %2;"
                 :: "r"(dst), "l"(__cvta_generic_to_global(src)), "r"(sz) : "memory");
}
#define CP_COMMIT() asm volatile("cp.async.commit_group;" ::: "memory")
#define CP_WAIT0()  asm volatile("cp.async.wait_group 0;" ::: "memory")
#define LDSM4(r, a) \
    asm volatile("ldmatrix.sync.aligned.m8n8.x4.shared.b16 {%0,%1,%2,%3}, [%4];" \
        : "=r"((r)[0]), "=r"((r)[1]), "=r"((r)[2]), "=r"((r)[3]) : "r"(a))

__device__ __forceinline__ void mma16816(float* c, const uint32_t* a,
                                         uint32_t b0, uint32_t b1) {
    asm volatile(
        "mma.sync.aligned.m16n8k16.row.col.f32.bf16.bf16.f32 "
        "{%0,%1,%2,%3}, {%4,%5,%6,%7}, {%8,%9}, {%0,%1,%2,%3};\n"
        : "+f"(c[0]), "+f"(c[1]), "+f"(c[2]), "+f"(c[3])
        : "r"(a[0]), "r"(a[1]), "r"(a[2]), "r"(a[3]), "r"(b0), "r"(b1));
}

// ---------------- CSR build --------------------------------------------------
__global__ void k_zero_count() {
    int i = blockIdx.x * blockDim.x + threadIdx.x;
    if (i < N1c) g_count[i] = 0;
}

__global__ void k_hist(const int* __restrict__ rows) {
    int i = blockIdx.x * blockDim.x + threadIdx.x;
    if (i < NNZc) atomicAdd(&g_count[rows[i]], 1);
}

__global__ void k_scan_a() {
    __shared__ int s[256];
    int tid  = threadIdx.x;
    int base = blockIdx.x * 2048;
    int vals[8];
    int sum = 0;
#pragma unroll
    for (int i = 0; i < 8; i++) {
        int idx = base + tid * 8 + i;
        int v = (idx < N1c) ? g_count[idx] : 0;
        vals[i] = sum;
        sum += v;
    }
    s[tid] = sum;
    __syncthreads();
    for (int off = 1; off < 256; off <<= 1) {
        int t = (tid >= off) ? s[tid - off] : 0;
        __syncthreads();
        s[tid] += t;
        __syncthreads();
    }
    int ex = s[tid] - sum;
#pragma unroll
    for (int i = 0; i < 8; i++) {
        int idx = base + tid * 8 + i;
        if (idx < N1c) g_start[idx] = ex + vals[i];
    }
    if (tid == 255) g_bsums[blockIdx.x] = s[255];
}

__global__ void k_scan_b(int nblk) {
    __shared__ int s[128];
    int tid = threadIdx.x;
    int v = (tid < nblk) ? g_bsums[tid] : 0;
    s[tid] = v;
    __syncthreads();
    for (int off = 1; off < 128; off <<= 1) {
        int t = (tid >= off) ? s[tid - off] : 0;
        __syncthreads();
        s[tid] += t;
        __syncthreads();
    }
    if (tid < nblk) g_bsums[tid] = s[tid] - v;
}

__global__ void k_scan_c() {
    int i = blockIdx.x * blockDim.x + threadIdx.x;
    if (i < N1c) {
        int v = g_start[i] + g_bsums[i >> 11];
        g_start[i]  = v;
        g_cursor[i] = v;
    }
}

__global__ void k_scatter(const int* __restrict__ rows, const int* __restrict__ cols,
                          const float* __restrict__ vals) {
    int e = blockIdx.x * blockDim.x + threadIdx.x;
    if (e < NNZc) {
        int p = atomicAdd(&g_cursor[rows[e]], 1);
        g_epack[p] = make_int2(cols[e], __float_as_int(vals[e]));
    }
}

// ---------------- prep: W transpose + bf16 hi/lo split -----------------------
__global__ void k_wprep(const float* __restrict__ W) {
    int i = blockIdx.x * 256 + threadIdx.x;      // 0..65535
    int n = i >> 8, k = i & 255;
    float v = W[k * Dc + n];
    __nv_bfloat16 h = __float2bfloat16(v);
    __nv_bfloat16 l = __float2bfloat16(v - __bfloat162float(h));
    g_WtH[i] = h;
    g_WtL[i] = l;
}

// ---------------- GEMM: msg = X @ W (bf16x3, fused fp32->bf16 split) ---------
// CTA: 64(M) x 256(N), BK=32, 256 threads (8 warps 2x4, warp tile 32x64),
// 2 CTAs/SM. X loaded raw fp32 (2-stage cp.async), converted to bf16 hi/lo
// in smem each stage (single conv buffer; 2 syncs/iter).
// 80B-padded rows: ldmatrix banks (20*i)%32 conflict-free.
#define RAW_STG  8192                // 64 x 32 fp32
#define B_SIDE   20480               // 256 x 40 bf16
#define B_STAGE  40960
#define OFF_B    16384               // 2 * RAW_STG
#define OFF_CAH  98304               // OFF_B + 2 * B_STAGE
#define OFF_CAL  103424              // OFF_CAH + 5120
#define GEMM_SMEM 108544

__device__ __forceinline__ void load_stage(uint32_t sb, int st, int m0, int tid,
                                           const float* X) {
    const int kb = st * 32;
    const uint32_t rawb = sb + (st & 1) * RAW_STG;
#pragma unroll
    for (int i = 0; i < 2; i++) {
        int idx = tid + (i << 8);
        int r = idx >> 3, c = idx & 7;
        int gm = m0 + r;
        int ok = (gm < N0c) ? 16 : 0;          // sz=0 -> zero-fill
        int rr = gm < N0c ? gm : N0c - 1;
        cp_async16(rawb + r * 128 + c * 16, X + (size_t)rr * Dc + kb + 4 * c, ok);
    }
    const uint32_t bb = sb + OFF_B + (st & 1) * B_STAGE;
#pragma unroll
    for (int i = 0; i < 8; i++) {
        int idx = tid + (i << 8);
        int side = idx >> 10, r = (idx >> 2) & 255, c = idx & 3;
        const __nv_bfloat16* src = (side ? g_WtL : g_WtH) + r * Dc + kb + 8 * c;
        cp_async16(bb + side * B_SIDE + r * 80 + c * 16, src, 16);
    }
}

__global__ __launch_bounds__(256, 2)
void k_gemm(const float* __restrict__ X) {
    extern __shared__ char smem[];
    const int tid = threadIdx.x;
    const int w = tid >> 5, l = tid & 31;
    const int m0 = blockIdx.x * 64;
    const uint32_t sb = smem_u32(smem);

    const int wm = (w >> 2) * 32;     // 2 (m) x 4 (n) warp grid, 32x64 tiles
    const int wn = (w & 3) * 64;
    const int ra  = (l & 7) + ((l >> 3) & 1) * 8;
    const int kca = (l >> 4) * 8;
    const int rb  = (l & 7) + (l >> 4) * 8;
    const int kcb = ((l >> 3) & 1) * 8;

    float acc[2][8][4];
#pragma unroll
    for (int a = 0; a < 2; a++)
#pragma unroll
        for (int b = 0; b < 8; b++)
#pragma unroll
            for (int c = 0; c < 4; c++) acc[a][b][c] = 0.f;

    load_stage(sb, 0, m0, tid, X); CP_COMMIT();

    for (int kt = 0; kt < 8; kt++) {
        CP_WAIT0();
        __syncthreads();                               // stage kt ready; prev compute done
        if (kt < 7) { load_stage(sb, kt + 1, m0, tid, X); CP_COMMIT(); }

        // convert raw fp32 stage kt -> bf16 hi/lo conv buffers
        {
            const char* rawp = smem + (kt & 1) * RAW_STG;
#pragma unroll
            for (int i = 0; i < 2; i++) {
                int idx = tid + (i << 8);
                int r = idx >> 3, c4 = (idx & 7) << 2;
                float4 v = *(const float4*)(rawp + r * 128 + (c4 << 2));
                float vv[4] = {v.x, v.y, v.z, v.w};
                uint32_t hp[2], lp[2];
#pragma unroll
                for (int j = 0; j < 2; j++) {
                    __nv_bfloat16 h0 = __float2bfloat16(vv[2 * j]);
                    __nv_bfloat16 h1 = __float2bfloat16(vv[2 * j + 1]);
                    __nv_bfloat16 l0 = __float2bfloat16(vv[2 * j] - __bfloat162float(h0));
                    __nv_bfloat16 l1 = __float2bfloat16(vv[2 * j + 1] - __bfloat162float(h1));
                    hp[j] = (uint32_t)__bfloat16_as_ushort(h0) | ((uint32_t)__bfloat16_as_ushort(h1) << 16);
                    lp[j] = (uint32_t)__bfloat16_as_ushort(l0) | ((uint32_t)__bfloat16_as_ushort(l1) << 16);
                }
                uint32_t off = r * 80 + (c4 << 1);
                *(uint2*)(smem + OFF_CAH + off) = make_uint2(hp[0], hp[1]);
                *(uint2*)(smem + OFF_CAL + off) = make_uint2(lp[0], lp[1]);
            }
        }
        __syncthreads();                               // conv buffers ready

        const uint32_t bbase = sb + OFF_B + (kt & 1) * B_STAGE;
#pragma unroll
        for (int k16 = 0; k16 < 32; k16 += 16) {
            uint32_t ah[2][4], al[2][4];
#pragma unroll
            for (int mi = 0; mi < 2; mi++) {
                uint32_t arow = sb + OFF_CAH + (wm + 16 * mi + ra) * 80 + (k16 + kca) * 2;
                LDSM4(ah[mi], arow);
                LDSM4(al[mi], arow + 5120);
            }
            uint32_t bh0[4], bl0[4], bh1[4], bl1[4];
            {
                uint32_t brow = bbase + (wn + rb) * 80 + (k16 + kcb) * 2;
                LDSM4(bh0, brow);
                LDSM4(bl0, brow + B_SIDE);
            }
#pragma unroll
            for (int ng = 0; ng < 4; ng++) {
                uint32_t* bh = (ng & 1) ? bh1 : bh0;
                uint32_t* bl = (ng & 1) ? bl1 : bl0;
                if (ng < 3) {
                    uint32_t* nh = (ng & 1) ? bh0 : bh1;
                    uint32_t* nl = (ng & 1) ? bl0 : bl1;
                    uint32_t brow = bbase + (wn + 16 * (ng + 1) + rb) * 80 + (k16 + kcb) * 2;
                    LDSM4(nh, brow);
                    LDSM4(nl, brow + B_SIDE);
                }
#pragma unroll
                for (int mi = 0; mi < 2; mi++) {
                    mma16816(acc[mi][2 * ng],     ah[mi], bh[0], bh[1]);
                    mma16816(acc[mi][2 * ng + 1], ah[mi], bh[2], bh[3]);
                }
#pragma unroll
                for (int mi = 0; mi < 2; mi++) {
                    mma16816(acc[mi][2 * ng],     al[mi], bh[0], bh[1]);
                    mma16816(acc[mi][2 * ng + 1], al[mi], bh[2], bh[3]);
                }
#pragma unroll
                for (int mi = 0; mi < 2; mi++) {
                    mma16816(acc[mi][2 * ng],     ah[mi], bl[0], bl[1]);
                    mma16816(acc[mi][2 * ng + 1], ah[mi], bl[2], bl[3]);
                }
            }
        }
    }

    // epilogue: acc -> g_msg
#pragma unroll
    for (int mi = 0; mi < 2; mi++) {
#pragma unroll
        for (int h = 0; h < 2; h++) {
            int row = m0 + wm + 16 * mi + (l >> 2) + 8 * h;
            if (row < N0c) {
                float* dst = &g_msg[(size_t)row * Dc + wn + 2 * (l & 3)];
#pragma unroll
                for (int nj = 0; nj < 8; nj++) {
                    float2 f = make_float2(acc[mi][nj][2 * h], acc[mi][nj][2 * h + 1]);
                    *(float2*)(dst + 8 * nj) = f;
                }
            }
        }
    }
}

// ---------------- pull aggregation + elu, one 128-col half per pass ----------
// Gathering only one half touches a 51.2MB line working set -> L2-resident.
// 32 threads per output row (4 floats each), 8 rows per 256-thread block.
__global__ void k_agg(float* __restrict__ out, int half) {
    int row = blockIdx.x * 8 + (threadIdx.x >> 5);
    int t = threadIdx.x & 31;
    if (row >= N1c) return;
    int s = g_start[row];
    int n = g_count[row];
    const float4* msg4 = (const float4*)g_msg;   // [row][64 float4s]
    const int off = half * 32 + t;               // float4 index within row
    float4 acc = make_float4(0.f, 0.f, 0.f, 0.f);
    int j = 0;
    for (; j + 2 <= n; j += 2) {                 // 2 independent gathers
        int2 e0 = g_epack[s + j];
        int2 e1 = g_epack[s + j + 1];
        float v0 = __int_as_float(e0.y);
        float v1 = __int_as_float(e1.y);
        float4 m0 = msg4[(size_t)e0.x * 64 + off];
        float4 m1 = msg4[(size_t)e1.x * 64 + off];
        acc.x += v0 * m0.x + v1 * m1.x;
        acc.y += v0 * m0.y + v1 * m1.y;
        acc.z += v0 * m0.z + v1 * m1.z;
        acc.w += v0 * m0.w + v1 * m1.w;
    }
    if (j < n) {
        int2 e = g_epack[s + j];
        float v = __int_as_float(e.y);
        float4 m = msg4[(size_t)e.x * 64 + off];
        acc.x += v * m.x;
        acc.y += v * m.y;
        acc.z += v * m.z;
        acc.w += v * m.w;
    }
    acc.x = acc.x > 0.f ? acc.x : expm1f(acc.x);
    acc.y = acc.y > 0.f ? acc.y : expm1f(acc.y);
    acc.z = acc.z > 0.f ? acc.z : expm1f(acc.z);
    acc.w = acc.w > 0.f ? acc.w : expm1f(acc.w);
    ((float4*)out)[(size_t)row * 64 + off] = acc;
}

// ---------------- launch ------------------------------------------------------
static cudaStream_t g_s1;
static cudaEvent_t  g_evFork, g_evCSR;

extern "C" void kernel_launch(void* const* d_in, const int* in_sizes, int n_in,
                              void* d_out, int out_size) {
    const float* x0   = (const float*)d_in[0];
    const int*   rows = (const int*)d_in[2];
    const int*   cols = (const int*)d_in[3];
    const float* vals = (const float*)d_in[4];
    const float* W    = (const float*)d_in[5];
    float* out = (float*)d_out;

    static bool once = []() {
        cudaFuncSetAttribute(k_gemm, cudaFuncAttributeMaxDynamicSharedMemorySize, GEMM_SMEM);
        cudaStreamCreateWithFlags(&g_s1, cudaStreamNonBlocking);
        cudaEventCreateWithFlags(&g_evFork, cudaEventDisableTiming);
        cudaEventCreateWithFlags(&g_evCSR, cudaEventDisableTiming);
        return true;
    }();
    (void)once;

    cudaEventRecord(g_evFork, 0);
    cudaStreamWaitEvent(g_s1, g_evFork, 0);

    // enqueue order keeps k_gemm at launch #4 (the slot ncu profiles)
    k_wprep<<<Dc, 256>>>(W);                                      // 1 (main)
    k_zero_count<<<(N1c + 255) / 256, 256, 0, g_s1>>>();          // 2 (s1)
    k_hist<<<(NNZc + 255) / 256, 256, 0, g_s1>>>(rows);           // 3 (s1)
    k_gemm<<<(N0c + 63) / 64, 256, GEMM_SMEM>>>(x0);              // 4 (main)
    k_scan_a<<<98, 256, 0, g_s1>>>();                             // 5 (s1)
    k_scan_b<<<1, 128, 0, g_s1>>>(98);                            // 6 (s1)
    k_scan_c<<<(N1c + 255) / 256, 256, 0, g_s1>>>();              // 7 (s1)
    k_scatter<<<(NNZc + 255) / 256, 256, 0, g_s1>>>(rows, cols, vals); // 8 (s1)
    cudaEventRecord(g_evCSR, g_s1);

    cudaStreamWaitEvent(0, g_evCSR, 0);
    // two sequential half passes: each gathers from an L2-resident 51.2MB set
    k_agg<<<(N1c + 7) / 8, 256>>>(out, 0);                        // 9
    k_agg<<<(N1c + 7) / 8, 256>>>(out, 1);                        // 10
}